// round 13
// baseline (speedup 1.0000x reference)
#include <cuda_runtime.h>
#include <cuda_fp16.h>
#include <cstdint>

#define NN 50000
#define NPAD 50176          // 392 * 128
#define DIM 512
#define BM 128
#define BK 64               // fp16 per k-chunk = 128 bytes per row
#define CHUNKS 8            // DIM / BK
#define STAGES 3
#define STAGE_BYTES 32768   // A 16KB + B 16KB
#define SMEM_TOTAL (STAGES * STAGE_BYTES)
#define RBLOCKS 224

typedef unsigned long long ull;

// ---------------- static device scratch (no allocation) ----------------
__device__ __align__(16) __half g_Ah [(size_t)NPAD * DIM];   // 51 MB  layer-1 A (fp16 x)
__device__ __align__(16) __half g_Ah2[(size_t)NPAD * DIM];   // 51 MB  layer-2 A
__device__ __align__(16) __half g_Z  [(size_t)NPAD * DIM];   // 51 MB  Z half (per layer, reused)
__device__ __align__(16) __half g_B1p[1024 * DIM];           // 1 MB  layer-1 W packed [self|neigh]
__device__ __align__(16) __half g_B2p[1024 * DIM];           // 1 MB  layer-2 W packed
__device__ float g_part16[2 * (size_t)NPAD * 16];            // FC partial slots
__device__ float g_bpart[2 * RBLOCKS];

// ---------------- PTX helpers ----------------
__device__ __forceinline__ uint32_t smem_u32(const void* p) {
    uint32_t a;
    asm("{ .reg .u64 t; cvta.to.shared.u64 t, %1; cvt.u32.u64 %0, t; }" : "=r"(a) : "l"(p));
    return a;
}
#define CP16(dst, src) asm volatile("cp.async.cg.shared.global [%0], [%1], 16;" :: "r"(dst), "l"(src))
#define CP_COMMIT()    asm volatile("cp.async.commit_group;" ::: "memory")
#define CP_WAIT(n)     asm volatile("cp.async.wait_group %0;" :: "n"(n) : "memory")

#define LDSM_X4(r0, r1, r2, r3, a) \
    asm volatile("ldmatrix.sync.aligned.m8n8.x4.shared.b16 {%0,%1,%2,%3}, [%4];" \
        : "=r"(r0), "=r"(r1), "=r"(r2), "=r"(r3) : "r"(a))

#define MMA16816(c, a, b) \
    asm volatile("mma.sync.aligned.m16n8k16.row.col.f32.f16.f16.f32 " \
        "{%0,%1,%2,%3}, {%4,%5,%6,%7}, {%8,%9}, {%0,%1,%2,%3};" \
        : "+f"((c)[0]), "+f"((c)[1]), "+f"((c)[2]), "+f"((c)[3]) \
        : "r"((a)[0]), "r"((a)[1]), "r"((a)[2]), "r"((a)[3]), "r"((b)[0]), "r"((b)[1]))

__device__ __forceinline__ float2 h2f(uint32_t u) { return __half22float2(*(__half2*)&u); }

// ---------------- fused prep: convert x -> fp16 + pack W1/W2 -> fp16 ----------------
#define CONV_BLOCKS (NPAD / 4)
__global__ void prep_kernel(const float* __restrict__ x,
                            const float* __restrict__ W1,
                            const float* __restrict__ W2) {
    int b = blockIdx.x;
    int tid = threadIdx.x;
    if (b < CONV_BLOCKS) {
        int i = b * 4 + (tid >> 6);
        int j = (tid & 63) * 8;
        __half* row = g_Ah + (size_t)i * DIM;
        if (i >= NN) { *(uint4*)(row + j) = make_uint4(0, 0, 0, 0); return; }
        float4 a = *(const float4*)(x + (size_t)i * DIM + j);
        float4 c = *(const float4*)(x + (size_t)i * DIM + j + 4);
        __half h[8] = { __float2half_rn(a.x), __float2half_rn(a.y),
                        __float2half_rn(a.z), __float2half_rn(a.w),
                        __float2half_rn(c.x), __float2half_rn(c.y),
                        __float2half_rn(c.z), __float2half_rn(c.w) };
        *(uint4*)(row + j) = *(uint4*)h;
    } else {
        int e = ((b - CONV_BLOCKS) * 256 + tid) * 4;       // 4 consecutive elems, same n
        int n = e >> 9, k = e & 511;
        int src = (n < DIM) ? (n * 1024 + k) : ((n - DIM) * 1024 + DIM + k);
        float4 w1 = *(const float4*)(W1 + src);
        float4 w2 = *(const float4*)(W2 + src);
        __half h1[4] = { __float2half_rn(w1.x), __float2half_rn(w1.y),
                         __float2half_rn(w1.z), __float2half_rn(w1.w) };
        __half h2[4] = { __float2half_rn(w2.x), __float2half_rn(w2.y),
                         __float2half_rn(w2.z), __float2half_rn(w2.w) };
        *(ull*)(g_B1p + e) = *(ull*)h1;
        *(ull*)(g_B2p + e) = *(ull*)h2;
    }
}

// ---------------- fp16 HMMA GEMM with fused epilogue ----------------
// CTA 128x128x64, warp tile 64x32, 3-stage cp.async pipeline, 2 CTAs/SM.
// MODE 0: Z-GEMM  (B neighbor half)        -> g_Z fp16
// MODE 1: Y1-GEMM (B self half) + combine  -> g_Ah2 fp16 (layer-2 A)
// MODE 2: Y2-GEMM (B self half) + combine + FC dot -> out fp32, g_part16
template<int MODE>
__global__ __launch_bounds__(256, 2) void gemm_kernel(
    int layer, const int* __restrict__ nbr,
    const float* __restrict__ fcw, float* __restrict__ out)
{
    extern __shared__ __align__(1024) char smem[];
    const uint32_t sbase = smem_u32(smem);
    const int tid = threadIdx.x;
    const int wid = tid >> 5;
    const int lane = tid & 31;
    const int wm = wid & 1;           // 2 warps along M
    const int wn = wid >> 1;          // 4 warps along N
    const __half* __restrict__ Bp = layer ? g_B2p : g_B1p;
    const __half* __restrict__ Ap = layer ? g_Ah2 : g_Ah;
    const size_t mBase = (size_t)blockIdx.y * BM;
    const int nOff = (MODE == 0) ? DIM : 0;        // neighbor vs self half of Bp

    const char* gA0 = (const char*)Ap + mBase * (DIM * 2);
    const char* gB0 = (const char*)Bp + (size_t)(nOff + blockIdx.x * 128) * (DIM * 2);

    auto load_chunk = [&](int kc, int s) {
        uint32_t sA = sbase + s * STAGE_BYTES;
        uint32_t sB = sA + 16384;
        const char* gA = gA0 + kc * 128;
        const char* gB = gB0 + kc * 128;
        #pragma unroll
        for (int i = 0; i < 4; i++) {
            int u = tid + i * 256;            // 0..1023
            int r = u >> 3, c = u & 7;
            uint32_t sw = (uint32_t)(r * 128 + (((c ^ (r & 7))) << 4));
            CP16(sA + sw, gA + (size_t)r * 1024 + c * 16);
            CP16(sB + sw, gB + (size_t)r * 1024 + c * 16);
        }
    };

    float acc[4][4][4];
    #pragma unroll
    for (int i = 0; i < 4; i++)
        #pragma unroll
        for (int j = 0; j < 4; j++)
            #pragma unroll
            for (int q = 0; q < 4; q++) acc[i][j][q] = 0.f;

    load_chunk(0, 0); CP_COMMIT();
    load_chunk(1, 1); CP_COMMIT();

    const int lrow = lane & 15;
    const int lhalf = lane >> 4;

    for (int kc = 0; kc < CHUNKS; kc++) {
        CP_WAIT(1);
        __syncthreads();

        uint32_t sA = sbase + (kc % STAGES) * STAGE_BYTES;
        uint32_t sB = sA + 16384;

        #pragma unroll
        for (int ks = 0; ks < 4; ks++) {
            uint32_t af[4][4], bf[4][2];
            #pragma unroll
            for (int am = 0; am < 4; am++) {
                int row = wm * 64 + am * 16 + lrow;
                int grp = ks * 2 + lhalf;
                uint32_t addr = sA + row * 128 + (((grp ^ (row & 7))) << 4);
                LDSM_X4(af[am][0], af[am][1], af[am][2], af[am][3], addr);
            }
            #pragma unroll
            for (int p = 0; p < 2; p++) {
                int row = wn * 32 + p * 16 + lrow;
                int grp = ks * 2 + lhalf;
                uint32_t addr = sB + row * 128 + (((grp ^ (row & 7))) << 4);
                uint32_t r0, r1, r2, r3;
                LDSM_X4(r0, r1, r2, r3, addr);
                bf[p * 2 + 0][0] = r0; bf[p * 2 + 0][1] = r2;
                bf[p * 2 + 1][0] = r1; bf[p * 2 + 1][1] = r3;
            }
            #pragma unroll
            for (int am = 0; am < 4; am++)
                #pragma unroll
                for (int bn = 0; bn < 4; bn++)
                    MMA16816(acc[am][bn], af[am], bf[bn]);
        }
        if (kc + 2 < CHUNKS) load_chunk(kc + 2, (kc + 2) % STAGES);
        CP_COMMIT();
    }

    const int crow = lane >> 2;
    const int ccol = (lane & 3) * 2;

    if (MODE == 0) {
        // plain fp16 store into g_Z (512-wide rows)
        #pragma unroll
        for (int am = 0; am < 4; am++) {
            size_t r0 = mBase + wm * 64 + am * 16 + crow;
            #pragma unroll
            for (int bn = 0; bn < 4; bn++) {
                int c0 = blockIdx.x * 128 + wn * 32 + bn * 8 + ccol;
                *(__half2*)(g_Z + r0 * DIM + c0) =
                    __floats2half2_rn(acc[am][bn][0], acc[am][bn][1]);
                *(__half2*)(g_Z + (r0 + 8) * DIM + c0) =
                    __floats2half2_rn(acc[am][bn][2], acc[am][bn][3]);
            }
        }
    } else {
        // fused combine epilogue: o = relu(Y + 0.5*(Z[n0]+Z[n1])), Y in fp32 regs
        const int nb = blockIdx.x * 128 + wn * 32;
        #pragma unroll
        for (int am = 0; am < 4; am++) {
            #pragma unroll
            for (int h = 0; h < 2; h++) {
                size_t r = mBase + wm * 64 + am * 16 + crow + h * 8;
                int i = (r < NN) ? (int)r : 0;
                int n0 = nbr[2 * i], n1 = nbr[2 * i + 1];
                float p0 = 0.f, p1 = 0.f;
                #pragma unroll
                for (int bn = 0; bn < 4; bn++) {
                    int c = nb + bn * 8 + ccol;
                    float y0 = acc[am][bn][h * 2 + 0];
                    float y1 = acc[am][bn][h * 2 + 1];
                    uint32_t za = *(const uint32_t*)(g_Z + (size_t)n0 * DIM + c);
                    uint32_t zb = *(const uint32_t*)(g_Z + (size_t)n1 * DIM + c);
                    float2 fa = h2f(za), fb = h2f(zb);
                    float o0 = fmaxf(fmaf(0.5f, fa.x + fb.x, y0), 0.f);
                    float o1 = fmaxf(fmaf(0.5f, fa.y + fb.y, y1), 0.f);
                    if (MODE == 1) {
                        *(__half2*)(g_Ah2 + r * DIM + c) = __floats2half2_rn(o0, o1);
                    } else if (r < NN) {
                        *(float2*)(out + (size_t)i * DIM + c) = make_float2(o0, o1);
                        float2 w0 = *(const float2*)(fcw + (size_t)i * DIM + c);
                        float2 w1 = *(const float2*)(fcw + (size_t)NN * DIM + (size_t)i * DIM + c);
                        p0 = fmaf(o0, w0.x, fmaf(o1, w0.y, p0));
                        p1 = fmaf(o0, w1.x, fmaf(o1, w1.y, p1));
                    }
                }
                if (MODE == 2) {
                    p0 += __shfl_xor_sync(0xFFFFFFFF, p0, 1);
                    p0 += __shfl_xor_sync(0xFFFFFFFF, p0, 2);
                    p1 += __shfl_xor_sync(0xFFFFFFFF, p1, 1);
                    p1 += __shfl_xor_sync(0xFFFFFFFF, p1, 2);
                    if ((lane & 3) == 0 && r < NN) {
                        int slot = blockIdx.x * 4 + wn;
                        g_part16[(size_t)i * 16 + slot] = p0;
                        g_part16[(size_t)NPAD * 16 + (size_t)i * 16 + slot] = p1;
                    }
                }
            }
        }
    }
}

// ---------------- final reduce stage 1: 224 blocks over nodes ----------------
__global__ void final_reduce_kernel() {
    int g = blockIdx.x * 256 + threadIdx.x;
    float a0 = 0.f, a1 = 0.f;
    for (int i = g; i < NN; i += RBLOCKS * 256) {
        const float* p = g_part16 + (size_t)i * 16;
        const float* q = g_part16 + (size_t)NPAD * 16 + (size_t)i * 16;
        float s0 = 0.f, s1 = 0.f;
        #pragma unroll
        for (int s = 0; s < 16; s++) { s0 += p[s]; s1 += q[s]; }
        a0 += s0; a1 += s1;
    }
    __shared__ float s0[256], s1[256];
    int tid = threadIdx.x;
    s0[tid] = a0; s1[tid] = a1;
    __syncthreads();
    #pragma unroll
    for (int st = 128; st > 0; st >>= 1) {
        if (tid < st) { s0[tid] += s0[tid + st]; s1[tid] += s1[tid + st]; }
        __syncthreads();
    }
    if (tid == 0) { g_bpart[blockIdx.x] = s0[0]; g_bpart[RBLOCKS + blockIdx.x] = s1[0]; }
}

// ---------------- final stage 2: bias + log_softmax ----------------
__global__ void final2_kernel(const float* __restrict__ fcb, float* __restrict__ out2) {
    __shared__ float s0[256], s1[256];
    int tid = threadIdx.x;
    float a = 0.f, b = 0.f;
    if (tid < RBLOCKS) { a = g_bpart[tid]; b = g_bpart[RBLOCKS + tid]; }
    s0[tid] = a; s1[tid] = b;
    __syncthreads();
    #pragma unroll
    for (int st = 128; st > 0; st >>= 1) {
        if (tid < st) { s0[tid] += s0[tid + st]; s1[tid] += s1[tid + st]; }
        __syncthreads();
    }
    if (tid == 0) {
        float l0 = s0[0] + fcb[0];
        float l1 = s1[0] + fcb[1];
        float m = fmaxf(l0, l1);
        float lse = m + logf(expf(l0 - m) + expf(l1 - m));
        out2[0] = l0 - lse;
        out2[1] = l1 - lse;
    }
}

// ---------------- launch ----------------
extern "C" void kernel_launch(void* const* d_in, const int* in_sizes, int n_in,
                              void* d_out, int out_size) {
    const float* x   = (const float*)d_in[0];
    const int*   nb1 = (const int*)  d_in[1];
    const int*   nb2 = (const int*)  d_in[2];
    const float* W1  = (const float*)d_in[3];
    const float* W2  = (const float*)d_in[4];
    const float* fcw = (const float*)d_in[5];
    const float* fcb = (const float*)d_in[6];
    float* out = (float*)d_out;

    cudaFuncSetAttribute(gemm_kernel<0>, cudaFuncAttributeMaxDynamicSharedMemorySize, SMEM_TOTAL);
    cudaFuncSetAttribute(gemm_kernel<1>, cudaFuncAttributeMaxDynamicSharedMemorySize, SMEM_TOTAL);
    cudaFuncSetAttribute(gemm_kernel<2>, cudaFuncAttributeMaxDynamicSharedMemorySize, SMEM_TOTAL);

    prep_kernel<<<CONV_BLOCKS + (1024 * DIM) / 1024, 256>>>(x, W1, W2);

    dim3 grid(4, NPAD / BM);                                       // (4, 392)
    gemm_kernel<0><<<grid, 256, SMEM_TOTAL>>>(0, nullptr, nullptr, nullptr);  // Z1 -> g_Z
    gemm_kernel<1><<<grid, 256, SMEM_TOTAL>>>(0, nb1, nullptr, nullptr);      // Y1+combine -> g_Ah2
    gemm_kernel<0><<<grid, 256, SMEM_TOTAL>>>(1, nullptr, nullptr, nullptr);  // Z2 -> g_Z
    gemm_kernel<2><<<grid, 256, SMEM_TOTAL>>>(1, nb2, fcw, out);              // Y2+combine+FC
    final_reduce_kernel<<<RBLOCKS, 256>>>();
    final2_kernel<<<1, 256>>>(fcb, out + (size_t)(out_size - 2));
}

// round 14
// speedup vs baseline: 1.1224x; 1.1224x over previous
#include <cuda_runtime.h>
#include <cuda_fp16.h>
#include <cstdint>

#define NN 50000
#define NPAD 50176          // 392 * 128
#define DIM 512
#define NCOL 1024
#define BM 128
#define BN 128
#define BK 64               // fp16 per k-chunk = 128 bytes per row
#define CHUNKS 8            // DIM / BK
#define STAGES 3
#define STAGE_BYTES 32768   // A 16KB + B 16KB
#define SMEM_TOTAL (STAGES * STAGE_BYTES)

typedef unsigned long long ull;

// ---------------- static device scratch (no allocation) ----------------
__device__ __align__(16) __half g_Ah[(size_t)NPAD * DIM];    // 51 MB  fp16 A
__device__ __align__(16) __half g_B1p[NCOL * DIM];           // 1 MB  Bh layer1
__device__ __align__(16) __half g_B2p[NCOL * DIM];           // 1 MB  Bh layer2
__device__ __align__(16) __half g_Ch[(size_t)NPAD * NCOL];   // 102 MB  fp16 C
__device__ float g_part[2 * NN];

// ---------------- PTX helpers ----------------
__device__ __forceinline__ uint32_t smem_u32(const void* p) {
    uint32_t a;
    asm("{ .reg .u64 t; cvta.to.shared.u64 t, %1; cvt.u32.u64 %0, t; }" : "=r"(a) : "l"(p));
    return a;
}
#define CP16(dst, src) asm volatile("cp.async.cg.shared.global [%0], [%1], 16;" :: "r"(dst), "l"(src))
#define CP_COMMIT()    asm volatile("cp.async.commit_group;" ::: "memory")
#define CP_WAIT(n)     asm volatile("cp.async.wait_group %0;" :: "n"(n) : "memory")

#define LDSM_X4(r0, r1, r2, r3, a) \
    asm volatile("ldmatrix.sync.aligned.m8n8.x4.shared.b16 {%0,%1,%2,%3}, [%4];" \
        : "=r"(r0), "=r"(r1), "=r"(r2), "=r"(r3) : "r"(a))

#define MMA16816(c, a, b) \
    asm volatile("mma.sync.aligned.m16n8k16.row.col.f32.f16.f16.f32 " \
        "{%0,%1,%2,%3}, {%4,%5,%6,%7}, {%8,%9}, {%0,%1,%2,%3};" \
        : "+f"((c)[0]), "+f"((c)[1]), "+f"((c)[2]), "+f"((c)[3]) \
        : "r"((a)[0]), "r"((a)[1]), "r"((a)[2]), "r"((a)[3]), "r"((b)[0]), "r"((b)[1]))

// ---------------- fused prep: convert x -> fp16 (blocks 0..NPAD/4-1),
//                  pack W1/W2 -> fp16 (blocks NPAD/4..NPAD/4+511) ----------------
#define CONV_BLOCKS (NPAD / 4)
__global__ void prep_kernel(const float* __restrict__ x,
                            const float* __restrict__ W1,
                            const float* __restrict__ W2) {
    int b = blockIdx.x;
    int tid = threadIdx.x;
    if (b < CONV_BLOCKS) {
        int i = b * 4 + (tid >> 6);
        int j = (tid & 63) * 8;
        __half* row = g_Ah + (size_t)i * DIM;
        if (i >= NN) { *(uint4*)(row + j) = make_uint4(0, 0, 0, 0); return; }
        float4 a = *(const float4*)(x + (size_t)i * DIM + j);
        float4 c = *(const float4*)(x + (size_t)i * DIM + j + 4);
        __half h[8] = { __float2half_rn(a.x), __float2half_rn(a.y),
                        __float2half_rn(a.z), __float2half_rn(a.w),
                        __float2half_rn(c.x), __float2half_rn(c.y),
                        __float2half_rn(c.z), __float2half_rn(c.w) };
        *(uint4*)(row + j) = *(uint4*)h;
    } else {
        int e = ((b - CONV_BLOCKS) * 256 + tid) * 4;       // 4 consecutive elems, same n
        int n = e >> 9, k = e & 511;
        int src = (n < DIM) ? (n * NCOL + k) : ((n - DIM) * NCOL + DIM + k);
        float4 w1 = *(const float4*)(W1 + src);
        float4 w2 = *(const float4*)(W2 + src);
        __half h1[4] = { __float2half_rn(w1.x), __float2half_rn(w1.y),
                         __float2half_rn(w1.z), __float2half_rn(w1.w) };
        __half h2[4] = { __float2half_rn(w2.x), __float2half_rn(w2.y),
                         __float2half_rn(w2.z), __float2half_rn(w2.w) };
        *(ull*)(g_B1p + e) = *(ull*)h1;
        *(ull*)(g_B2p + e) = *(ull*)h2;
    }
}

// ---------------- fp16 HMMA GEMM: g_Ch[M,1024] = A[M,512] @ B^T ----------------
// CTA 128x128x64, warp tile 64x32, 3-stage cp.async pipeline, 2 CTAs/SM.
// k-loop fully unrolled: stage slots and swizzle offsets become immediates.
__global__ __launch_bounds__(256, 2) void gemm_kernel(int layer) {
    extern __shared__ __align__(1024) char smem[];
    const uint32_t sbase = smem_u32(smem);
    const int tid = threadIdx.x;
    const int wid = tid >> 5;
    const int lane = tid & 31;
    const int wm = wid & 1;           // 2 warps along M
    const int wn = wid >> 1;          // 4 warps along N
    const __half* __restrict__ Bp = layer ? g_B2p : g_B1p;
    const size_t mBase = (size_t)blockIdx.y * BM;
    const int nBase = blockIdx.x * BN;

    const char* gA0 = (const char*)g_Ah + mBase * (DIM * 2);
    const char* gB0 = (const char*)Bp + (size_t)nBase * (DIM * 2);

    auto load_chunk = [&](int kc, int s) {
        uint32_t sA = sbase + s * STAGE_BYTES;
        uint32_t sB = sA + 16384;
        const char* gA = gA0 + kc * 128;
        const char* gB = gB0 + kc * 128;
        #pragma unroll
        for (int i = 0; i < 4; i++) {
            int u = tid + i * 256;            // 0..1023
            int r = u >> 3, c = u & 7;
            uint32_t sw = (uint32_t)(r * 128 + (((c ^ (r & 7))) << 4));
            CP16(sA + sw, gA + (size_t)r * 1024 + c * 16);
            CP16(sB + sw, gB + (size_t)r * 1024 + c * 16);
        }
    };

    float acc[4][4][4];
    #pragma unroll
    for (int i = 0; i < 4; i++)
        #pragma unroll
        for (int j = 0; j < 4; j++)
            #pragma unroll
            for (int q = 0; q < 4; q++) acc[i][j][q] = 0.f;

    load_chunk(0, 0); CP_COMMIT();
    load_chunk(1, 1); CP_COMMIT();

    const int lrow = lane & 15;       // row within 16
    const int lhalf = lane >> 4;      // k-half

    #pragma unroll
    for (int kc = 0; kc < CHUNKS; kc++) {
        CP_WAIT(1);                   // chunk kc resident
        __syncthreads();

        uint32_t sA = sbase + (kc % STAGES) * STAGE_BYTES;
        uint32_t sB = sA + 16384;

        #pragma unroll
        for (int ks = 0; ks < 4; ks++) {
            uint32_t af[4][4], bf[4][2];
            #pragma unroll
            for (int am = 0; am < 4; am++) {
                int row = wm * 64 + am * 16 + lrow;
                int grp = ks * 2 + lhalf;
                uint32_t addr = sA + row * 128 + (((grp ^ (row & 7))) << 4);
                LDSM_X4(af[am][0], af[am][1], af[am][2], af[am][3], addr);
            }
            #pragma unroll
            for (int p = 0; p < 2; p++) {
                int row = wn * 32 + p * 16 + lrow;
                int grp = ks * 2 + lhalf;
                uint32_t addr = sB + row * 128 + (((grp ^ (row & 7))) << 4);
                uint32_t r0, r1, r2, r3;
                LDSM_X4(r0, r1, r2, r3, addr);
                bf[p * 2 + 0][0] = r0; bf[p * 2 + 0][1] = r2;
                bf[p * 2 + 1][0] = r1; bf[p * 2 + 1][1] = r3;
            }
            #pragma unroll
            for (int am = 0; am < 4; am++)
                #pragma unroll
                for (int bn = 0; bn < 4; bn++)
                    MMA16816(acc[am][bn], af[am], bf[bn]);
        }
        if (kc + 2 < CHUNKS) load_chunk(kc + 2, (kc + 2) % STAGES);
        CP_COMMIT();
    }

    // epilogue: fp16 store. c frag m16n8 -> (row = l>>2 [+8], col = (l&3)*2)
    const int crow = lane >> 2;
    const int ccol = (lane & 3) * 2;
    #pragma unroll
    for (int am = 0; am < 4; am++) {
        size_t r0 = mBase + wm * 64 + am * 16 + crow;
        #pragma unroll
        for (int bn = 0; bn < 4; bn++) {
            int c0 = nBase + wn * 32 + bn * 8 + ccol;
            __half2* p0 = (__half2*)(g_Ch + r0 * NCOL + c0);
            __half2* p1 = (__half2*)(g_Ch + (r0 + 8) * NCOL + c0);
            *p0 = __floats2half2_rn(acc[am][bn][0], acc[am][bn][1]);
            *p1 = __floats2half2_rn(acc[am][bn][2], acc[am][bn][3]);
        }
    }
}

// ---------------- layer-1 combine -> fp16: A <- relu(Y + 0.5*(Z0+Z1)) ----------------
__device__ __forceinline__ float2 h2f(uint32_t u) { return __half22float2(*(__half2*)&u); }

// 4 rows per 256-thread block; 64 threads per row, 8 halves each (16B loads).
__global__ void combine1_kernel(const int* __restrict__ neighs) {
    int i = blockIdx.x * 4 + (threadIdx.x >> 6);
    int j = (threadIdx.x & 63) * 8;
    __half* row = g_Ah + (size_t)i * DIM;
    if (i >= NN) { *(uint4*)(row + j) = make_uint4(0, 0, 0, 0); return; }
    int n0 = neighs[2 * i], n1 = neighs[2 * i + 1];
    uint4 ys = *(const uint4*)(g_Ch + (size_t)i  * NCOL + j);
    uint4 z0 = *(const uint4*)(g_Ch + (size_t)n0 * NCOL + DIM + j);
    uint4 z1 = *(const uint4*)(g_Ch + (size_t)n1 * NCOL + DIM + j);
    const uint32_t* yp = &ys.x;
    const uint32_t* p0 = &z0.x;
    const uint32_t* p1 = &z1.x;
    __half h[8];
    #pragma unroll
    for (int q = 0; q < 4; q++) {
        float2 s = h2f(yp[q]), a0 = h2f(p0[q]), a1 = h2f(p1[q]);
        h[q * 2 + 0] = __float2half_rn(fmaxf(fmaf(0.5f, a0.x + a1.x, s.x), 0.f));
        h[q * 2 + 1] = __float2half_rn(fmaxf(fmaf(0.5f, a0.y + a1.y, s.y), 0.f));
    }
    *(uint4*)(row + j) = *(uint4*)h;
}

// ---------------- layer-2 combine fused with FC-head partial dots ----------------
// 8 rows per 512-thread block; 2 warps per row.
__global__ void combine2_kernel(const int* __restrict__ neighs,
                                const float* __restrict__ fcw,
                                float* __restrict__ out) {
    int tid = threadIdx.x;
    int i = blockIdx.x * 8 + (tid >> 6);
    int j = (tid & 63) * 8;
    int n0 = neighs[2 * i], n1 = neighs[2 * i + 1];
    uint4 ys = *(const uint4*)(g_Ch + (size_t)i  * NCOL + j);
    uint4 z0 = *(const uint4*)(g_Ch + (size_t)n0 * NCOL + DIM + j);
    uint4 z1 = *(const uint4*)(g_Ch + (size_t)n1 * NCOL + DIM + j);
    const uint32_t* yp = &ys.x;
    const uint32_t* p0 = &z0.x;
    const uint32_t* p1 = &z1.x;
    size_t idx = (size_t)i * DIM + j;
    float o[8];
    #pragma unroll
    for (int q = 0; q < 4; q++) {
        float2 s = h2f(yp[q]), a0 = h2f(p0[q]), a1 = h2f(p1[q]);
        o[q * 2 + 0] = fmaxf(fmaf(0.5f, a0.x + a1.x, s.x), 0.f);
        o[q * 2 + 1] = fmaxf(fmaf(0.5f, a0.y + a1.y, s.y), 0.f);
    }
    *(float4*)(out + idx) = make_float4(o[0], o[1], o[2], o[3]);
    *(float4*)(out + idx + 4) = make_float4(o[4], o[5], o[6], o[7]);

    float p0s = 0.f, p1s = 0.f;
    #pragma unroll
    for (int half = 0; half < 2; half++) {
        float4 w0 = *(const float4*)(fcw + idx + half * 4);
        float4 w1 = *(const float4*)(fcw + (size_t)NN * DIM + idx + half * 4);
        const float* ov = o + half * 4;
        p0s += ov[0] * w0.x + ov[1] * w0.y + ov[2] * w0.z + ov[3] * w0.w;
        p1s += ov[0] * w1.x + ov[1] * w1.y + ov[2] * w1.z + ov[3] * w1.w;
    }

    // warp shuffle reduce (deterministic), then pair-combine the 2 warps per row
    #pragma unroll
    for (int st = 16; st > 0; st >>= 1) {
        p0s += __shfl_down_sync(0xFFFFFFFF, p0s, st);
        p1s += __shfl_down_sync(0xFFFFFFFF, p1s, st);
    }
    __shared__ float s0[16], s1[16];
    int w = tid >> 5;
    if ((tid & 31) == 0) { s0[w] = p0s; s1[w] = p1s; }
    __syncthreads();
    if ((tid & 63) == 0) {
        g_part[i]      = s0[w] + s0[w + 1];
        g_part[NN + i] = s1[w] + s1[w + 1];
    }
}

// ---------------- final: deterministic reduce + bias + log_softmax ----------------
__global__ void final_kernel(const float* __restrict__ fcb, float* __restrict__ out2) {
    __shared__ float s0[256], s1[256];
    int tid = threadIdx.x;
    float a = 0.f, b = 0.f;
    for (int i = tid; i < NN; i += 256) { a += g_part[i]; b += g_part[NN + i]; }
    s0[tid] = a; s1[tid] = b;
    __syncthreads();
    #pragma unroll
    for (int st = 128; st > 0; st >>= 1) {
        if (tid < st) { s0[tid] += s0[tid + st]; s1[tid] += s1[tid + st]; }
        __syncthreads();
    }
    if (tid == 0) {
        float l0 = s0[0] + fcb[0];
        float l1 = s1[0] + fcb[1];
        float m = fmaxf(l0, l1);
        float lse = m + logf(expf(l0 - m) + expf(l1 - m));
        out2[0] = l0 - lse;
        out2[1] = l1 - lse;
    }
}

// ---------------- launch ----------------
extern "C" void kernel_launch(void* const* d_in, const int* in_sizes, int n_in,
                              void* d_out, int out_size) {
    const float* x   = (const float*)d_in[0];
    const int*   nb1 = (const int*)  d_in[1];
    const int*   nb2 = (const int*)  d_in[2];
    const float* W1  = (const float*)d_in[3];
    const float* W2  = (const float*)d_in[4];
    const float* fcw = (const float*)d_in[5];
    const float* fcb = (const float*)d_in[6];
    float* out = (float*)d_out;

    cudaFuncSetAttribute(gemm_kernel, cudaFuncAttributeMaxDynamicSharedMemorySize, SMEM_TOTAL);

    prep_kernel<<<CONV_BLOCKS + (NCOL * DIM) / 1024, 256>>>(x, W1, W2);

    dim3 grid(NCOL / BN, NPAD / BM);                       // (8, 392)
    gemm_kernel<<<grid, 256, SMEM_TOTAL>>>(0);             // layer 1 -> g_Ch
    combine1_kernel<<<NPAD / 4, 256>>>(nb1);               // -> g_Ah (fp16)
    gemm_kernel<<<grid, 256, SMEM_TOTAL>>>(1);             // layer 2 -> g_Ch
    combine2_kernel<<<NN / 8, 512>>>(nb2, fcw, out);       // flat -> d_out, FC partials
    final_kernel<<<1, 256>>>(fcb, out + (size_t)(out_size - 2));
}